// round 15
// baseline (speedup 1.0000x reference)
#include <cuda_runtime.h>
#include <cuda_fp16.h>
#include <cstdint>

// Problem constants
#define NB 2
#define HH 16
#define TT 2048
#define DD 1024
#define SS 64
// exp2-domain constants: log2(e) folded into Q scale and mask multiplier
#define QSCALE 0.1803368801111204f      // 0.125 * log2(e)
#define MASKSCALE -1.442695040e9f       // NEG_INF * log2(e)

// Scratch (device globals; no runtime allocation). All fp16, pre-rounded.
// Packings (pos8 on half2 pairs within 16-element k-groups):
//  g_Aq/g_Ar/g_Oh : [m][(k&~15) + pos8((k>>1)&7)*2 + (k&1)]
//  g_Wh           : [z][kg=k>>4][n][8 half2 in pos8 order]
//  g_Qh/g_Kh      : [n][h][t][(s&~15) + pos8((s>>1)&7)*2 + (s&1)]
//  g_Vh           : [n][h][tg=t>>4][s][8 half2: (V[2j][s],V[2j+1][s]) at pos8(j)]
__device__ __half g_Qh[NB * HH * TT * SS];
__device__ __half g_Kh[NB * HH * TT * SS];
__device__ __half g_Vh[NB * HH * TT * SS];
__device__ __half g_Oh[NB * TT * DD];
__device__ __half g_Aq[NB * TT * DD];
__device__ __half g_Ar[NB * TT * DD];
__device__ __half g_Wh[4 * DD * DD];

__device__ __forceinline__ int pos8(int j) { return (j & 3) * 2 + (j >> 2); }

__device__ __forceinline__ uint32_t h2u(float a, float b) {
    __half2 h = __floats2half2_rn(a, b);
    return *reinterpret_cast<uint32_t*>(&h);
}

__device__ __forceinline__ float ex2(float x) {
    float y;
    asm("ex2.approx.f32 %0, %1;" : "=f"(y) : "f"(x));
    return y;
}

__device__ __forceinline__ void mma_f16(float* c, const uint32_t* a,
                                        uint32_t b0, uint32_t b1) {
    asm volatile(
        "mma.sync.aligned.m16n8k16.row.col.f32.f16.f16.f32 "
        "{%0,%1,%2,%3}, {%4,%5,%6,%7}, {%8,%9}, {%0,%1,%2,%3};\n"
        : "+f"(c[0]), "+f"(c[1]), "+f"(c[2]), "+f"(c[3])
        : "r"(a[0]), "r"(a[1]), "r"(a[2]), "r"(a[3]), "r"(b0), "r"(b1));
}

__device__ __forceinline__ void cp16(void* smem_dst, const void* gsrc) {
    uint32_t d = (uint32_t)__cvta_generic_to_shared(smem_dst);
    asm volatile("cp.async.cg.shared.global [%0], [%1], 16;\n" :: "r"(d), "l"(gsrc));
}
__device__ __forceinline__ void l2_prefetch(const void* p) {
    asm volatile("prefetch.global.L2 [%0];" :: "l"(p));
}
__device__ __forceinline__ uint32_t smem_u32(const void* p) {
    return (uint32_t)__cvta_generic_to_shared(p);
}

#define MBAR_INIT(a, c) \
    asm volatile("mbarrier.init.shared.b64 [%0], %1;" :: "r"(a), "r"(c) : "memory")
#define MBAR_ARRIVE(a) \
    asm volatile("mbarrier.arrive.shared.b64 _, [%0];" :: "r"(a) : "memory")
#define CP_MBAR_ARRIVE(a) \
    asm volatile("cp.async.mbarrier.arrive.noinc.shared.b64 [%0];" :: "r"(a) : "memory")
#define MBAR_WAIT(a, par) do {                                                  \
    uint32_t _m = (a), _p = (par);                                              \
    asm volatile("{\n\t.reg .pred P1;\n\t"                                      \
        "WL_%=:\n\t"                                                            \
        "mbarrier.try_wait.parity.acquire.cta.shared::cta.b64 P1, [%0], %1, 0x989680;\n\t" \
        "@P1 bra.uni WD_%=;\n\t"                                                \
        "bra.uni WL_%=;\n\t"                                                    \
        "WD_%=:\n\t}" :: "r"(_m), "r"(_p) : "memory");                          \
} while (0)

// ============================================================================
// Prep: activations f32 -> packed fp16. Thread handles 16 consecutive k.
// ============================================================================
__global__ void __launch_bounds__(256) prep_act(const float* __restrict__ q,
                                                const float* __restrict__ r) {
    const float* src = blockIdx.z ? r : q;
    __half* dst = blockIdx.z ? g_Ar : g_Aq;
    size_t idx = (size_t)blockIdx.x * 256 + threadIdx.x;
    size_t m = idx >> 6;
    int k0 = (int)(idx & 63) * 16;
    float f[16];
    const float* s = src + m * DD + k0;
#pragma unroll
    for (int i = 0; i < 4; i++) *(float4*)(f + i * 4) = *(const float4*)(s + i * 4);
    uint32_t hh[8];
#pragma unroll
    for (int j = 0; j < 8; j++) hh[pos8(j)] = h2u(f[2 * j], f[2 * j + 1]);
    __half* d = dst + m * DD + k0;
    *(uint4*)d = make_uint4(hh[0], hh[1], hh[2], hh[3]);
    *(uint4*)(d + 8) = make_uint4(hh[4], hh[5], hh[6], hh[7]);
}

// Prep: weights f32 [k][n] -> g_Wh [z][kg][n][8 half2 pos8 order]
__global__ void __launch_bounds__(256) prep_w(
    const float* __restrict__ W0, const float* __restrict__ W1,
    const float* __restrict__ W2, const float* __restrict__ W3) {
    const int z = blockIdx.z;
    const float* W = (z == 0) ? W0 : (z == 1) ? W1 : (z == 2) ? W2 : W3;
    size_t idx = (size_t)blockIdx.x * 256 + threadIdx.x;
    int kg = (int)(idx >> 10), n = (int)(idx & 1023);
    float f[16];
#pragma unroll
    for (int i = 0; i < 16; i++) f[i] = W[(size_t)(kg * 16 + i) * DD + n];
    uint32_t hh[8];
#pragma unroll
    for (int j = 0; j < 8; j++) hh[pos8(j)] = h2u(f[2 * j], f[2 * j + 1]);
    __half* d = g_Wh + (size_t)z * DD * DD + ((size_t)kg * 1024 + n) * 16;
    *(uint4*)d = make_uint4(hh[0], hh[1], hh[2], hh[3]);
    *(uint4*)(d + 8) = make_uint4(hh[4], hh[5], hh[6], hh[7]);
}

// ============================================================================
// fp16 GEMM, mbarrier 4-stage pipeline (unchanged from R12 pass).
// mode 0: z in {0,1,2}: A = g_Aq/g_Ar, B = g_Wh[z] -> scatter packed Q/K/V fp16
// mode 1: A = g_Oh, B = g_Wh[3] -> f32 row-major into outp
// ============================================================================
#define GSTGH 10240
#define GEMM_SMEM (4 * GSTGH * 2 + 64)

__global__ void __launch_bounds__(256, 2) gemm_f16_kernel(
    float* __restrict__ outp, int mode)
{
    extern __shared__ __half smh[];
    const uint32_t mb_full = smem_u32(smh) + 4 * GSTGH * 2;
    const uint32_t mb_empty = mb_full + 32;

    const int z = blockIdx.z;
    const __half* A = (mode == 1) ? g_Oh : (z == 0 ? g_Aq : g_Ar);
    const __half* B = g_Wh + (size_t)((mode == 1) ? 3 : z) * DD * DD;

    const int tid = threadIdx.x;
    const int lane = tid & 31, warp = tid >> 5;
    const int la3 = lane & 3, q4 = lane >> 2;
    const int wm = warp & 3, wn = warp >> 2;
    const int m0 = blockIdx.y * 128, n0 = blockIdx.x * 128;

    if (tid == 0) {
#pragma unroll
        for (int s = 0; s < 4; s++) {
            MBAR_INIT(mb_full + s * 8, 256);
            MBAR_INIT(mb_empty + s * 8, 256);
        }
    }
    __syncthreads();

    float c[2][8][4];
#pragma unroll
    for (int mt = 0; mt < 2; mt++)
#pragma unroll
        for (int nt = 0; nt < 8; nt++)
#pragma unroll
            for (int i = 0; i < 4; i++) c[mt][nt][i] = 0.f;

    int pstage = 0, pphase = 1;
    int cstage = 0, cphase = 0;

    auto producer = [&](int t) {
        MBAR_WAIT(mb_empty + pstage * 8, pphase);
        __half* base = smh + pstage * GSTGH;
        const int k0 = t * 32;
#pragma unroll
        for (int i = 0; i < 2; i++) {
            int lin = tid + i * 256;
            int r = lin >> 2, cc = lin & 3;
            cp16(base + r * 48 + cc * 8, A + (size_t)(m0 + r) * DD + k0 + cc * 8);
        }
#pragma unroll
        for (int i = 0; i < 2; i++) {
            int lin = tid + i * 256;
            int kgl = lin >> 8, n = (lin >> 1) & 127, hf = lin & 1;
            cp16(base + 6144 + (kgl * 128 + n) * 16 + hf * 8,
                 B + ((size_t)((k0 >> 4) + kgl) * 1024 + n0 + n) * 16 + hf * 8);
        }
        CP_MBAR_ARRIVE(mb_full + pstage * 8);
        if (++pstage == 4) { pstage = 0; pphase ^= 1; }
    };

    producer(0); producer(1); producer(2);

    for (int t = 0; t < 32; t++) {
        if (t + 3 < 32) producer(t + 3);
        MBAR_WAIT(mb_full + cstage * 8, cphase);

        const __half* Ab = smh + cstage * GSTGH;
        const __half* Bb = Ab + 6144;
#pragma unroll
        for (int kg = 0; kg < 2; kg++) {
            uint32_t a[2][4];
#pragma unroll
            for (int mt = 0; mt < 2; mt++) {
                int r = wm * 32 + mt * 16 + q4;
                uint2 lo = *(const uint2*)(Ab + r * 48 + kg * 16 + 4 * la3);
                uint2 hi = *(const uint2*)(Ab + (r + 8) * 48 + kg * 16 + 4 * la3);
                a[mt][0] = lo.x; a[mt][2] = lo.y;
                a[mt][1] = hi.x; a[mt][3] = hi.y;
            }
#pragma unroll
            for (int nt = 0; nt < 8; nt++) {
                int cc = wn * 64 + nt * 8 + q4;
                uint2 b = *(const uint2*)(Bb + (kg * 128 + cc) * 16 + 4 * la3);
                mma_f16(c[0][nt], a[0], b.x, b.y);
                mma_f16(c[1][nt], a[1], b.x, b.y);
            }
        }
        MBAR_ARRIVE(mb_empty + cstage * 8);
        if (++cstage == 4) { cstage = 0; cphase ^= 1; }
    }

    const float scale = (mode == 0 && z == 0) ? QSCALE : 1.0f;
#pragma unroll
    for (int mt = 0; mt < 2; mt++) {
        int row = m0 + wm * 32 + mt * 16 + q4;
#pragma unroll
        for (int nt = 0; nt < 8; nt++) {
            int col = n0 + wn * 64 + nt * 8 + 2 * la3;
#pragma unroll
            for (int half = 0; half < 2; half++) {
                int r = row + half * 8;
                float v0 = c[mt][nt][half * 2 + 0] * scale;
                float v1 = c[mt][nt][half * 2 + 1] * scale;
                if (mode == 1) {
                    *(float2*)&outp[(size_t)r * DD + col] = make_float2(v0, v1);
                } else {
                    int nn = r >> 11, t = r & 2047;
                    int h = col >> 6, s = col & 63;
                    size_t hb = (size_t)(nn * HH + h) * TT * SS;
                    if (z == 2) {
                        int p = pos8((t >> 1) & 7);
                        size_t h2i = hb / 2 + ((size_t)(t >> 4) * 64 + s) * 8 + p;
                        g_Vh[h2i * 2 + (t & 1)]      = __float2half_rn(v0);
                        g_Vh[h2i * 2 + 16 + (t & 1)] = __float2half_rn(v1);
                    } else {
                        __half* dstb = (z == 0) ? g_Qh : g_Kh;
                        int j = (s >> 1) & 7;
                        size_t ha = hb + (size_t)t * SS + (s & ~15) + 2 * pos8(j);
                        *(uint32_t*)&dstb[ha] = h2u(v0, v1);
                    }
                }
            }
        }
    }
}

// ============================================================================
// Flash attention fp16 v7: 128 threads, 4 warps x 32 q-rows (2 m-tiles) —
// K/V fragment loads hoisted across m-tiles => smem crossbar traffic per FLOP
// halved. 3 CTAs/SM. exp2-domain softmax. mbarrier 4-stage K/V pipeline.
// ============================================================================
#define FSTGH 9216
#define FLASH_SMEM (4 * FSTGH * 2 + 64)   // 73792 bytes

__global__ void __launch_bounds__(128, 3) flash_kernel(const float* __restrict__ mask)
{
    extern __shared__ __half sh[];
    const uint32_t mb_full = smem_u32(sh) + 4 * FSTGH * 2;
    const uint32_t mb_empty = mb_full + 32;

    const int tid = threadIdx.x;
    const int lane = tid & 31, warp = tid >> 5;
    const int la3 = lane & 3, q4 = lane >> 2;
    const int qt = blockIdx.x, h = blockIdx.y, n = blockIdx.z;
    const int q0 = qt * 128;
    const size_t headbase = ((size_t)(n * HH + h)) * TT * SS;   // half units

    if (tid == 0) {
#pragma unroll
        for (int s = 0; s < 4; s++) {
            MBAR_INIT(mb_full + s * 8, 128);
            MBAR_INIT(mb_empty + s * 8, 128);
        }
    }
    __syncthreads();

    int pstage = 0, pphase = 1;
    int cstage = 0, cphase = 0;

    auto producer = [&](int t) {
        MBAR_WAIT(mb_empty + pstage * 8, pphase);
        __half* Kd = sh + pstage * FSTGH;
        __half* Vd = Kd + 5120;
#pragma unroll
        for (int i = 0; i < 4; i++) {
            int lin = tid + i * 128;
            int r = lin >> 3, cc = lin & 7;
            cp16(Kd + r * 80 + cc * 8,
                 g_Kh + headbase + (size_t)(t * 64 + r) * SS + cc * 8);
        }
#pragma unroll
        for (int i = 0; i < 4; i++) {
            int lin = tid + i * 128;
            cp16(Vd + lin * 8, g_Vh + headbase + (size_t)t * 4096 + lin * 8);
        }
        CP_MBAR_ARRIVE(mb_full + pstage * 8);
        if (++pstage == 4) { pstage = 0; pphase ^= 1; }
    };

    // Per-warp mask base: 32 rows starting at q0 + warp*32
    const float* mwarp =
        mask + (((size_t)(n * HH + h)) * TT + q0 + warp * 32) * TT;
    const float* mbase = mwarp + (size_t)q4 * TT;

    // Q fragments straight from gmem (packed layout = native uint2 frags)
    uint32_t qa[2][4][4];
#pragma unroll
    for (int mt = 0; mt < 2; mt++) {
        const int rr = q0 + warp * 32 + mt * 16 + q4;
#pragma unroll
        for (int ks = 0; ks < 4; ks++) {
            const __half* qrow = g_Qh + headbase + (size_t)rr * SS + ks * 16 + 4 * la3;
            uint2 lo = *(const uint2*)qrow;
            uint2 hi = *(const uint2*)(qrow + 8 * SS);
            qa[mt][ks][0] = lo.x; qa[mt][ks][2] = lo.y;
            qa[mt][ks][1] = hi.x; qa[mt][ks][3] = hi.y;
        }
    }

    producer(0); producer(1); producer(2);
    l2_prefetch(mwarp + (size_t)lane * TT);
    l2_prefetch(mwarp + (size_t)lane * TT + 32);

    float o[2][8][4];
#pragma unroll
    for (int mt = 0; mt < 2; mt++)
#pragma unroll
        for (int nt = 0; nt < 8; nt++)
#pragma unroll
            for (int i = 0; i < 4; i++) o[mt][nt][i] = 0.f;
    float mr[4] = {-INFINITY, -INFINITY, -INFINITY, -INFINITY};  // [mt*2+half]
    float lr[4] = {0.f, 0.f, 0.f, 0.f};

    for (int j = 0; j < 32; j++) {
        const int k0 = j * 64;

        // Mask -> score init in exp2 domain (LDGs issue before any waits)
        float sc[2][8][4];
#pragma unroll
        for (int mt = 0; mt < 2; mt++) {
            const float* mrow = mbase + (size_t)(mt * 16) * TT;
#pragma unroll
            for (int nt = 0; nt < 8; nt++) {
                int col = k0 + nt * 8 + 2 * la3;
                float2 m0v = *(const float2*)(mrow + col);
                float2 m1v = *(const float2*)(mrow + (size_t)8 * TT + col);
                sc[mt][nt][0] = m0v.x * MASKSCALE;
                sc[mt][nt][1] = m0v.y * MASKSCALE;
                sc[mt][nt][2] = m1v.x * MASKSCALE;
                sc[mt][nt][3] = m1v.y * MASKSCALE;
            }
        }

        if (j + 3 < 32) producer(j + 3);
        if (j + 1 < 32) {
            l2_prefetch(mwarp + (size_t)lane * TT + (j + 1) * 64);
            l2_prefetch(mwarp + (size_t)lane * TT + (j + 1) * 64 + 32);
        }

        MBAR_WAIT(mb_full + cstage * 8, cphase);
        const __half* Kc = sh + cstage * FSTGH;
        const __half* Vc = Kc + 5120;

        // sc += Q * K^T  (K frag loaded ONCE, used by both m-tiles)
#pragma unroll
        for (int nt = 0; nt < 8; nt++) {
            int key = nt * 8 + q4;
#pragma unroll
            for (int ks = 0; ks < 4; ks++) {
                uint2 b = *(const uint2*)(Kc + key * 80 + ks * 16 + 4 * la3);
                mma_f16(sc[0][nt], qa[0][ks], b.x, b.y);
                mma_f16(sc[1][nt], qa[1][ks], b.x, b.y);
            }
        }

        // Online softmax (exp2 domain); rescale only when max changes
        float t4[4] = {-INFINITY, -INFINITY, -INFINITY, -INFINITY};
#pragma unroll
        for (int mt = 0; mt < 2; mt++)
#pragma unroll
            for (int nt = 0; nt < 8; nt++) {
                t4[mt * 2 + 0] = fmaxf(t4[mt * 2 + 0], fmaxf(sc[mt][nt][0], sc[mt][nt][1]));
                t4[mt * 2 + 1] = fmaxf(t4[mt * 2 + 1], fmaxf(sc[mt][nt][2], sc[mt][nt][3]));
            }
#pragma unroll
        for (int i = 0; i < 4; i++) {
            t4[i] = fmaxf(t4[i], __shfl_xor_sync(0xffffffffu, t4[i], 1));
            t4[i] = fmaxf(t4[i], __shfl_xor_sync(0xffffffffu, t4[i], 2));
        }

        bool need = (t4[0] > mr[0]) || (t4[1] > mr[1]) || (t4[2] > mr[2]) || (t4[3] > mr[3]);
        if (__ballot_sync(0xffffffffu, need)) {
            float cor[4];
#pragma unroll
            for (int i = 0; i < 4; i++) {
                float nm = fmaxf(mr[i], t4[i]);
                cor[i] = ex2(mr[i] - nm);
                mr[i] = nm;
                lr[i] *= cor[i];
            }
#pragma unroll
            for (int mt = 0; mt < 2; mt++)
#pragma unroll
                for (int nt = 0; nt < 8; nt++) {
                    o[mt][nt][0] *= cor[mt * 2];     o[mt][nt][1] *= cor[mt * 2];
                    o[mt][nt][2] *= cor[mt * 2 + 1]; o[mt][nt][3] *= cor[mt * 2 + 1];
                }
        }

#pragma unroll
        for (int mt = 0; mt < 2; mt++) {
            float s0 = 0.f, s1 = 0.f;
#pragma unroll
            for (int nt = 0; nt < 8; nt++) {
                sc[mt][nt][0] = ex2(sc[mt][nt][0] - mr[mt * 2]);
                sc[mt][nt][1] = ex2(sc[mt][nt][1] - mr[mt * 2]);
                sc[mt][nt][2] = ex2(sc[mt][nt][2] - mr[mt * 2 + 1]);
                sc[mt][nt][3] = ex2(sc[mt][nt][3] - mr[mt * 2 + 1]);
                s0 += sc[mt][nt][0] + sc[mt][nt][1];
                s1 += sc[mt][nt][2] + sc[mt][nt][3];
            }
            lr[mt * 2] += s0;       // cross-lane reduce deferred to end
            lr[mt * 2 + 1] += s1;
        }

        // O += P * V : V frag loaded ONCE, used by both m-tiles
#pragma unroll
        for (int ks = 0; ks < 4; ks++) {
            uint32_t pa0[4], pa1[4];
            pa0[0] = h2u(sc[0][2 * ks][0], sc[0][2 * ks][1]);
            pa0[1] = h2u(sc[0][2 * ks][2], sc[0][2 * ks][3]);
            pa0[2] = h2u(sc[0][2 * ks + 1][0], sc[0][2 * ks + 1][1]);
            pa0[3] = h2u(sc[0][2 * ks + 1][2], sc[0][2 * ks + 1][3]);
            pa1[0] = h2u(sc[1][2 * ks][0], sc[1][2 * ks][1]);
            pa1[1] = h2u(sc[1][2 * ks][2], sc[1][2 * ks][3]);
            pa1[2] = h2u(sc[1][2 * ks + 1][0], sc[1][2 * ks + 1][1]);
            pa1[3] = h2u(sc[1][2 * ks + 1][2], sc[1][2 * ks + 1][3]);
#pragma unroll
            for (int nt = 0; nt < 8; nt++) {
                int s = nt * 8 + q4;
                uint2 b = *(const uint2*)(Vc + (ks * 64 + s) * 16 + 4 * la3);
                mma_f16(o[0][nt], pa0, b.x, b.y);
                mma_f16(o[1][nt], pa1, b.x, b.y);
            }
        }

        MBAR_ARRIVE(mb_empty + cstage * 8);
        if (++cstage == 4) { cstage = 0; cphase ^= 1; }
    }

    // Final cross-lane l reduction
#pragma unroll
    for (int i = 0; i < 4; i++) {
        lr[i] += __shfl_xor_sync(0xffffffffu, lr[i], 1);
        lr[i] += __shfl_xor_sync(0xffffffffu, lr[i], 2);
    }

    // Normalize, write g_Oh packed fp16 (feeds out-proj GEMM A)
#pragma unroll
    for (int mt = 0; mt < 2; mt++) {
        float i0 = 1.f / lr[mt * 2], i1 = 1.f / lr[mt * 2 + 1];
        int r = q0 + warp * 32 + mt * 16 + q4;
        size_t ob0 = ((size_t)n * TT + r) * DD;
        size_t ob1 = ((size_t)n * TT + r + 8) * DD;
#pragma unroll
        for (int nt = 0; nt < 8; nt++) {
            int off = h * SS + (nt >> 1) * 16 + 2 * (2 * la3 + (nt & 1));
            *(uint32_t*)&g_Oh[ob0 + off] = h2u(o[mt][nt][0] * i0, o[mt][nt][1] * i0);
            *(uint32_t*)&g_Oh[ob1 + off] = h2u(o[mt][nt][2] * i1, o[mt][nt][3] * i1);
        }
    }
}

// ============================================================================
// Launch
// ============================================================================
extern "C" void kernel_launch(void* const* d_in, const int* in_sizes, int n_in,
                              void* d_out, int out_size)
{
    const float* qseq = (const float*)d_in[0];
    const float* rseq = (const float*)d_in[1];
    const float* mask = (const float*)d_in[2];
    const float* Wq   = (const float*)d_in[3];
    const float* Wk   = (const float*)d_in[4];
    const float* Wv   = (const float*)d_in[5];
    const float* Wo   = (const float*)d_in[6];
    float* out = (float*)d_out;

    cudaFuncSetAttribute(gemm_f16_kernel, cudaFuncAttributeMaxDynamicSharedMemorySize,
                         GEMM_SMEM);
    cudaFuncSetAttribute(flash_kernel, cudaFuncAttributeMaxDynamicSharedMemorySize,
                         FLASH_SMEM);

    // Prep: f32 -> packed fp16
    prep_act<<<dim3(1024, 1, 2), 256>>>(qseq, rseq);
    prep_w<<<dim3(256, 1, 4), 256>>>(Wq, Wk, Wv, Wo);

    // QKV projections fused into one launch over z (Q scale includes log2e)
    gemm_f16_kernel<<<dim3(8, 32, 3), 256, GEMM_SMEM>>>(nullptr, 0);

    // Flash attention (128 threads, 3 CTAs/SM)
    flash_kernel<<<dim3(16, HH, NB), 128, FLASH_SMEM>>>(mask);

    // Output projection -> d_out
    gemm_f16_kernel<<<dim3(8, 32, 1), 256, GEMM_SMEM>>>(out, 1);
}

// round 16
// speedup vs baseline: 1.4985x; 1.4985x over previous
#include <cuda_runtime.h>
#include <cuda_fp16.h>
#include <cstdint>

// Problem constants
#define NB 2
#define HH 16
#define TT 2048
#define DD 1024
#define SS 64
// exp2-domain constants: log2(e) folded into Q scale and mask multiplier
#define QSCALE 0.1803368801111204f      // 0.125 * log2(e)
#define MASKSCALE -1.442695040e9f       // NEG_INF * log2(e)

// Scratch (device globals; no runtime allocation). All fp16, pre-rounded.
// Packings (pos8 on half2 pairs within 16-element k-groups):
//  g_Aq/g_Ar/g_Oh : [m][(k&~15) + pos8((k>>1)&7)*2 + (k&1)]
//  g_Wh           : [z][kg=k>>4][n][8 half2 in pos8 order]
//  g_Qh/g_Kh      : [n][h][t][(s&~15) + pos8((s>>1)&7)*2 + (s&1)]
//  g_Vh           : [n][h][tg=t>>4][s][8 half2: (V[2j][s],V[2j+1][s]) at pos8(j)]
__device__ __half g_Qh[NB * HH * TT * SS];
__device__ __half g_Kh[NB * HH * TT * SS];
__device__ __half g_Vh[NB * HH * TT * SS];
__device__ __half g_Oh[NB * TT * DD];
__device__ __half g_Aq[NB * TT * DD];
__device__ __half g_Ar[NB * TT * DD];
__device__ __half g_Wh[4 * DD * DD];

__device__ __forceinline__ int pos8(int j) { return (j & 3) * 2 + (j >> 2); }

__device__ __forceinline__ uint32_t h2u(float a, float b) {
    __half2 h = __floats2half2_rn(a, b);
    return *reinterpret_cast<uint32_t*>(&h);
}

__device__ __forceinline__ float ex2(float x) {
    float y;
    asm("ex2.approx.f32 %0, %1;" : "=f"(y) : "f"(x));
    return y;
}

__device__ __forceinline__ void mma_f16(float* c, const uint32_t* a,
                                        uint32_t b0, uint32_t b1) {
    asm volatile(
        "mma.sync.aligned.m16n8k16.row.col.f32.f16.f16.f32 "
        "{%0,%1,%2,%3}, {%4,%5,%6,%7}, {%8,%9}, {%0,%1,%2,%3};\n"
        : "+f"(c[0]), "+f"(c[1]), "+f"(c[2]), "+f"(c[3])
        : "r"(a[0]), "r"(a[1]), "r"(a[2]), "r"(a[3]), "r"(b0), "r"(b1));
}

__device__ __forceinline__ void cp16(void* smem_dst, const void* gsrc) {
    uint32_t d = (uint32_t)__cvta_generic_to_shared(smem_dst);
    asm volatile("cp.async.cg.shared.global [%0], [%1], 16;\n" :: "r"(d), "l"(gsrc));
}
__device__ __forceinline__ uint32_t smem_u32(const void* p) {
    return (uint32_t)__cvta_generic_to_shared(p);
}

#define MBAR_INIT(a, c) \
    asm volatile("mbarrier.init.shared.b64 [%0], %1;" :: "r"(a), "r"(c) : "memory")
#define MBAR_ARRIVE(a) \
    asm volatile("mbarrier.arrive.shared.b64 _, [%0];" :: "r"(a) : "memory")
#define CP_MBAR_ARRIVE(a) \
    asm volatile("cp.async.mbarrier.arrive.noinc.shared.b64 [%0];" :: "r"(a) : "memory")
#define MBAR_WAIT(a, par) do {                                                  \
    uint32_t _m = (a), _p = (par);                                              \
    asm volatile("{\n\t.reg .pred P1;\n\t"                                      \
        "WL_%=:\n\t"                                                            \
        "mbarrier.try_wait.parity.acquire.cta.shared::cta.b64 P1, [%0], %1, 0x989680;\n\t" \
        "@P1 bra.uni WD_%=;\n\t"                                                \
        "bra.uni WL_%=;\n\t"                                                    \
        "WD_%=:\n\t}" :: "r"(_m), "r"(_p) : "memory");                          \
} while (0)

// ============================================================================
// Prep: activations f32 -> packed fp16. Thread handles 16 consecutive k.
// ============================================================================
__global__ void __launch_bounds__(256) prep_act(const float* __restrict__ q,
                                                const float* __restrict__ r) {
    const float* src = blockIdx.z ? r : q;
    __half* dst = blockIdx.z ? g_Ar : g_Aq;
    size_t idx = (size_t)blockIdx.x * 256 + threadIdx.x;
    size_t m = idx >> 6;
    int k0 = (int)(idx & 63) * 16;
    float f[16];
    const float* s = src + m * DD + k0;
#pragma unroll
    for (int i = 0; i < 4; i++) *(float4*)(f + i * 4) = *(const float4*)(s + i * 4);
    uint32_t hh[8];
#pragma unroll
    for (int j = 0; j < 8; j++) hh[pos8(j)] = h2u(f[2 * j], f[2 * j + 1]);
    __half* d = dst + m * DD + k0;
    *(uint4*)d = make_uint4(hh[0], hh[1], hh[2], hh[3]);
    *(uint4*)(d + 8) = make_uint4(hh[4], hh[5], hh[6], hh[7]);
}

// Prep: weights f32 [k][n] -> g_Wh [z][kg][n][8 half2 pos8 order]
__global__ void __launch_bounds__(256) prep_w(
    const float* __restrict__ W0, const float* __restrict__ W1,
    const float* __restrict__ W2, const float* __restrict__ W3) {
    const int z = blockIdx.z;
    const float* W = (z == 0) ? W0 : (z == 1) ? W1 : (z == 2) ? W2 : W3;
    size_t idx = (size_t)blockIdx.x * 256 + threadIdx.x;
    int kg = (int)(idx >> 10), n = (int)(idx & 1023);
    float f[16];
#pragma unroll
    for (int i = 0; i < 16; i++) f[i] = W[(size_t)(kg * 16 + i) * DD + n];
    uint32_t hh[8];
#pragma unroll
    for (int j = 0; j < 8; j++) hh[pos8(j)] = h2u(f[2 * j], f[2 * j + 1]);
    __half* d = g_Wh + (size_t)z * DD * DD + ((size_t)kg * 1024 + n) * 16;
    *(uint4*)d = make_uint4(hh[0], hh[1], hh[2], hh[3]);
    *(uint4*)(d + 8) = make_uint4(hh[4], hh[5], hh[6], hh[7]);
}

// ============================================================================
// fp16 GEMM, mbarrier 4-stage pipeline (exact R12 winner).
// mode 0: z in {0,1,2}: A = g_Aq/g_Ar, B = g_Wh[z] -> scatter packed Q/K/V fp16
// mode 1: A = g_Oh, B = g_Wh[3] -> f32 row-major into outp
// ============================================================================
#define GSTGH 10240
#define GEMM_SMEM (4 * GSTGH * 2 + 64)

__global__ void __launch_bounds__(256, 2) gemm_f16_kernel(
    float* __restrict__ outp, int mode)
{
    extern __shared__ __half smh[];
    const uint32_t mb_full = smem_u32(smh) + 4 * GSTGH * 2;
    const uint32_t mb_empty = mb_full + 32;

    const int z = blockIdx.z;
    const __half* A = (mode == 1) ? g_Oh : (z == 0 ? g_Aq : g_Ar);
    const __half* B = g_Wh + (size_t)((mode == 1) ? 3 : z) * DD * DD;

    const int tid = threadIdx.x;
    const int lane = tid & 31, warp = tid >> 5;
    const int la3 = lane & 3, q4 = lane >> 2;
    const int wm = warp & 3, wn = warp >> 2;
    const int m0 = blockIdx.y * 128, n0 = blockIdx.x * 128;

    if (tid == 0) {
#pragma unroll
        for (int s = 0; s < 4; s++) {
            MBAR_INIT(mb_full + s * 8, 256);
            MBAR_INIT(mb_empty + s * 8, 256);
        }
    }
    __syncthreads();

    float c[2][8][4];
#pragma unroll
    for (int mt = 0; mt < 2; mt++)
#pragma unroll
        for (int nt = 0; nt < 8; nt++)
#pragma unroll
            for (int i = 0; i < 4; i++) c[mt][nt][i] = 0.f;

    int pstage = 0, pphase = 1;
    int cstage = 0, cphase = 0;

    auto producer = [&](int t) {
        MBAR_WAIT(mb_empty + pstage * 8, pphase);
        __half* base = smh + pstage * GSTGH;
        const int k0 = t * 32;
#pragma unroll
        for (int i = 0; i < 2; i++) {
            int lin = tid + i * 256;
            int r = lin >> 2, cc = lin & 3;
            cp16(base + r * 48 + cc * 8, A + (size_t)(m0 + r) * DD + k0 + cc * 8);
        }
#pragma unroll
        for (int i = 0; i < 2; i++) {
            int lin = tid + i * 256;
            int kgl = lin >> 8, n = (lin >> 1) & 127, hf = lin & 1;
            cp16(base + 6144 + (kgl * 128 + n) * 16 + hf * 8,
                 B + ((size_t)((k0 >> 4) + kgl) * 1024 + n0 + n) * 16 + hf * 8);
        }
        CP_MBAR_ARRIVE(mb_full + pstage * 8);
        if (++pstage == 4) { pstage = 0; pphase ^= 1; }
    };

    producer(0); producer(1); producer(2);

    for (int t = 0; t < 32; t++) {
        if (t + 3 < 32) producer(t + 3);
        MBAR_WAIT(mb_full + cstage * 8, cphase);

        const __half* Ab = smh + cstage * GSTGH;
        const __half* Bb = Ab + 6144;
#pragma unroll
        for (int kg = 0; kg < 2; kg++) {
            uint32_t a[2][4];
#pragma unroll
            for (int mt = 0; mt < 2; mt++) {
                int r = wm * 32 + mt * 16 + q4;
                uint2 lo = *(const uint2*)(Ab + r * 48 + kg * 16 + 4 * la3);
                uint2 hi = *(const uint2*)(Ab + (r + 8) * 48 + kg * 16 + 4 * la3);
                a[mt][0] = lo.x; a[mt][2] = lo.y;
                a[mt][1] = hi.x; a[mt][3] = hi.y;
            }
#pragma unroll
            for (int nt = 0; nt < 8; nt++) {
                int cc = wn * 64 + nt * 8 + q4;
                uint2 b = *(const uint2*)(Bb + (kg * 128 + cc) * 16 + 4 * la3);
                mma_f16(c[0][nt], a[0], b.x, b.y);
                mma_f16(c[1][nt], a[1], b.x, b.y);
            }
        }
        MBAR_ARRIVE(mb_empty + cstage * 8);
        if (++cstage == 4) { cstage = 0; cphase ^= 1; }
    }

    const float scale = (mode == 0 && z == 0) ? QSCALE : 1.0f;
#pragma unroll
    for (int mt = 0; mt < 2; mt++) {
        int row = m0 + wm * 32 + mt * 16 + q4;
#pragma unroll
        for (int nt = 0; nt < 8; nt++) {
            int col = n0 + wn * 64 + nt * 8 + 2 * la3;
#pragma unroll
            for (int half = 0; half < 2; half++) {
                int r = row + half * 8;
                float v0 = c[mt][nt][half * 2 + 0] * scale;
                float v1 = c[mt][nt][half * 2 + 1] * scale;
                if (mode == 1) {
                    *(float2*)&outp[(size_t)r * DD + col] = make_float2(v0, v1);
                } else {
                    int nn = r >> 11, t = r & 2047;
                    int h = col >> 6, s = col & 63;
                    size_t hb = (size_t)(nn * HH + h) * TT * SS;
                    if (z == 2) {
                        int p = pos8((t >> 1) & 7);
                        size_t h2i = hb / 2 + ((size_t)(t >> 4) * 64 + s) * 8 + p;
                        g_Vh[h2i * 2 + (t & 1)]      = __float2half_rn(v0);
                        g_Vh[h2i * 2 + 16 + (t & 1)] = __float2half_rn(v1);
                    } else {
                        __half* dstb = (z == 0) ? g_Qh : g_Kh;
                        int j = (s >> 1) & 7;
                        size_t ha = hb + (size_t)t * SS + (s & ~15) + 2 * pos8(j);
                        *(uint32_t*)&dstb[ha] = h2u(v0, v1);
                    }
                }
            }
        }
    }
}

// ============================================================================
// Flash attention fp16 v8: 256 threads, 16 q-rows/warp (R12 shape), with the
// MASK TILE inside the cp.async pipeline (coalesced) instead of scattered LDG.
// Stage = K(10240B) + V(8192B) + mask 128x64 f32 pitch 72 (36864B) = 55296B.
// 2 stages, 2 CTAs/SM. exp2-domain softmax.
// ============================================================================
#define FSTGB 55296
#define FMOFF 18432                      // mask byte offset within stage
#define FLASH_SMEM (2 * FSTGB + 64)      // 110656 bytes

__global__ void __launch_bounds__(256, 2) flash_kernel(const float* __restrict__ mask)
{
    extern __shared__ char shb[];
    const uint32_t mb_full = smem_u32(shb) + 2 * FSTGB;
    const uint32_t mb_empty = mb_full + 16;

    const int tid = threadIdx.x;
    const int lane = tid & 31, warp = tid >> 5;
    const int la3 = lane & 3, q4 = lane >> 2;
    const int qt = blockIdx.x, h = blockIdx.y, n = blockIdx.z;
    const int q0 = qt * 128;
    const size_t headbase = ((size_t)(n * HH + h)) * TT * SS;   // half units
    const float* mcta = mask + (((size_t)(n * HH + h)) * TT + q0) * TT;

    if (tid == 0) {
#pragma unroll
        for (int s = 0; s < 2; s++) {
            MBAR_INIT(mb_full + s * 8, 256);
            MBAR_INIT(mb_empty + s * 8, 256);
        }
    }
    __syncthreads();

    int pstage = 0, pphase = 1;
    int cstage = 0, cphase = 0;

    auto producer = [&](int t) {
        MBAR_WAIT(mb_empty + pstage * 8, pphase);
        char* base = shb + pstage * FSTGB;
        __half* Kd = (__half*)base;
        __half* Vd = Kd + 5120;
        float* Md = (float*)(base + FMOFF);
        // K: 64 rows x 80-pitch halfs (data 64x64)
#pragma unroll
        for (int i = 0; i < 2; i++) {
            int lin = tid + i * 256;
            int r = lin >> 3, cc = lin & 7;
            cp16(Kd + r * 80 + cc * 8,
                 g_Kh + headbase + (size_t)(t * 64 + r) * SS + cc * 8);
        }
        // V: 4096 halfs
#pragma unroll
        for (int i = 0; i < 2; i++) {
            int lin = tid + i * 256;
            cp16(Vd + lin * 8, g_Vh + headbase + (size_t)t * 4096 + lin * 8);
        }
        // Mask: 128 rows x 64 f32 (16 chunks/row), pitch 72 f32
#pragma unroll
        for (int i = 0; i < 8; i++) {
            int lin = tid + i * 256;
            int r = lin >> 4, ch = lin & 15;
            cp16(Md + r * 72 + ch * 4, mcta + (size_t)r * TT + t * 64 + ch * 4);
        }
        CP_MBAR_ARRIVE(mb_full + pstage * 8);
        if (++pstage == 2) { pstage = 0; pphase ^= 1; }
    };

    const int r0 = warp * 16 + q4;

    // Q fragments straight from gmem (packed layout = native uint2 frags)
    uint32_t qa[4][4];
#pragma unroll
    for (int ks = 0; ks < 4; ks++) {
        const __half* qrow = g_Qh + headbase + (size_t)(q0 + r0) * SS + ks * 16 + 4 * la3;
        uint2 lo = *(const uint2*)qrow;
        uint2 hi = *(const uint2*)(qrow + 8 * SS);
        qa[ks][0] = lo.x; qa[ks][2] = lo.y;
        qa[ks][1] = hi.x; qa[ks][3] = hi.y;
    }

    producer(0); producer(1);

    float o[8][4];
#pragma unroll
    for (int nt = 0; nt < 8; nt++)
#pragma unroll
        for (int i = 0; i < 4; i++) o[nt][i] = 0.f;
    float mr0 = -INFINITY, mr1 = -INFINITY;
    float lr0 = 0.f, lr1 = 0.f;

    for (int j = 0; j < 32; j++) {
        MBAR_WAIT(mb_full + cstage * 8, cphase);
        const char* base = shb + cstage * FSTGB;
        const __half* Kc = (const __half*)base;
        const __half* Vc = Kc + 5120;
        const float* Mc = (const float*)(base + FMOFF);

        // Mask -> score init (conflict-free LDS.64, exp2 domain)
        float sc[8][4];
#pragma unroll
        for (int nt = 0; nt < 8; nt++) {
            int col = nt * 8 + 2 * la3;
            float2 m0v = *(const float2*)(Mc + r0 * 72 + col);
            float2 m1v = *(const float2*)(Mc + (r0 + 8) * 72 + col);
            sc[nt][0] = m0v.x * MASKSCALE;
            sc[nt][1] = m0v.y * MASKSCALE;
            sc[nt][2] = m1v.x * MASKSCALE;
            sc[nt][3] = m1v.y * MASKSCALE;
        }

        // sc += Q * K^T
#pragma unroll
        for (int nt = 0; nt < 8; nt++) {
            int key = nt * 8 + q4;
#pragma unroll
            for (int ks = 0; ks < 4; ks++) {
                uint2 b = *(const uint2*)(Kc + key * 80 + ks * 16 + 4 * la3);
                mma_f16(sc[nt], qa[ks], b.x, b.y);
            }
        }

        // Online softmax (exp2 domain); rescale only when max changes
        float t0 = -INFINITY, t1 = -INFINITY;
#pragma unroll
        for (int nt = 0; nt < 8; nt++) {
            t0 = fmaxf(t0, fmaxf(sc[nt][0], sc[nt][1]));
            t1 = fmaxf(t1, fmaxf(sc[nt][2], sc[nt][3]));
        }
        t0 = fmaxf(t0, __shfl_xor_sync(0xffffffffu, t0, 1));
        t0 = fmaxf(t0, __shfl_xor_sync(0xffffffffu, t0, 2));
        t1 = fmaxf(t1, __shfl_xor_sync(0xffffffffu, t1, 1));
        t1 = fmaxf(t1, __shfl_xor_sync(0xffffffffu, t1, 2));

        bool need = (t0 > mr0) || (t1 > mr1);
        if (__ballot_sync(0xffffffffu, need)) {
            float nm0 = fmaxf(mr0, t0), nm1 = fmaxf(mr1, t1);
            float cor0 = ex2(mr0 - nm0), cor1 = ex2(mr1 - nm1);
            mr0 = nm0; mr1 = nm1;
            lr0 *= cor0; lr1 *= cor1;
#pragma unroll
            for (int nt = 0; nt < 8; nt++) {
                o[nt][0] *= cor0; o[nt][1] *= cor0;
                o[nt][2] *= cor1; o[nt][3] *= cor1;
            }
        }

        float s0 = 0.f, s1 = 0.f;
#pragma unroll
        for (int nt = 0; nt < 8; nt++) {
            sc[nt][0] = ex2(sc[nt][0] - mr0);
            sc[nt][1] = ex2(sc[nt][1] - mr0);
            sc[nt][2] = ex2(sc[nt][2] - mr1);
            sc[nt][3] = ex2(sc[nt][3] - mr1);
            s0 += sc[nt][0] + sc[nt][1];
            s1 += sc[nt][2] + sc[nt][3];
        }
        lr0 += s0;   // cross-lane reduce deferred to end
        lr1 += s1;

        // O += P * V : P straight from sc registers
#pragma unroll
        for (int ks = 0; ks < 4; ks++) {
            uint32_t pa[4];
            pa[0] = h2u(sc[2 * ks][0], sc[2 * ks][1]);
            pa[1] = h2u(sc[2 * ks][2], sc[2 * ks][3]);
            pa[2] = h2u(sc[2 * ks + 1][0], sc[2 * ks + 1][1]);
            pa[3] = h2u(sc[2 * ks + 1][2], sc[2 * ks + 1][3]);
#pragma unroll
            for (int nt = 0; nt < 8; nt++) {
                int s = nt * 8 + q4;
                uint2 b = *(const uint2*)(Vc + (ks * 64 + s) * 16 + 4 * la3);
                mma_f16(o[nt], pa, b.x, b.y);
            }
        }

        MBAR_ARRIVE(mb_empty + cstage * 8);
        if (++cstage == 2) { cstage = 0; cphase ^= 1; }

        // Produce tile j+2 into the just-freed stage (after consumption)
        if (j + 2 < 32) producer(j + 2);
    }

    // Final cross-lane l reduction
    lr0 += __shfl_xor_sync(0xffffffffu, lr0, 1);
    lr0 += __shfl_xor_sync(0xffffffffu, lr0, 2);
    lr1 += __shfl_xor_sync(0xffffffffu, lr1, 1);
    lr1 += __shfl_xor_sync(0xffffffffu, lr1, 2);

    // Normalize, write g_Oh packed fp16 (feeds out-proj GEMM A)
    float i0 = 1.f / lr0, i1 = 1.f / lr1;
    int r = q0 + warp * 16 + q4;
    size_t ob0 = ((size_t)n * TT + r) * DD;
    size_t ob1 = ((size_t)n * TT + r + 8) * DD;
#pragma unroll
    for (int nt = 0; nt < 8; nt++) {
        int off = h * SS + (nt >> 1) * 16 + 2 * (2 * la3 + (nt & 1));
        *(uint32_t*)&g_Oh[ob0 + off] = h2u(o[nt][0] * i0, o[nt][1] * i0);
        *(uint32_t*)&g_Oh[ob1 + off] = h2u(o[nt][2] * i1, o[nt][3] * i1);
    }
}

// ============================================================================
// Launch
// ============================================================================
extern "C" void kernel_launch(void* const* d_in, const int* in_sizes, int n_in,
                              void* d_out, int out_size)
{
    const float* qseq = (const float*)d_in[0];
    const float* rseq = (const float*)d_in[1];
    const float* mask = (const float*)d_in[2];
    const float* Wq   = (const float*)d_in[3];
    const float* Wk   = (const float*)d_in[4];
    const float* Wv   = (const float*)d_in[5];
    const float* Wo   = (const float*)d_in[6];
    float* out = (float*)d_out;

    cudaFuncSetAttribute(gemm_f16_kernel, cudaFuncAttributeMaxDynamicSharedMemorySize,
                         GEMM_SMEM);
    cudaFuncSetAttribute(flash_kernel, cudaFuncAttributeMaxDynamicSharedMemorySize,
                         FLASH_SMEM);

    // Prep: f32 -> packed fp16
    prep_act<<<dim3(1024, 1, 2), 256>>>(qseq, rseq);
    prep_w<<<dim3(256, 1, 4), 256>>>(Wq, Wk, Wv, Wo);

    // QKV projections fused into one launch over z (Q scale includes log2e)
    gemm_f16_kernel<<<dim3(8, 32, 3), 256, GEMM_SMEM>>>(nullptr, 0);

    // Flash attention (256 threads, 2 CTAs/SM, mask in cp.async pipeline)
    flash_kernel<<<dim3(16, HH, NB), 256, FLASH_SMEM>>>(mask);

    // Output projection -> d_out
    gemm_f16_kernel<<<dim3(8, 32, 1), 256, GEMM_SMEM>>>(out, 1);
}